// round 1
// baseline (speedup 1.0000x reference)
#include <cuda_runtime.h>
#include <cstdint>
#include <math.h>

// Problem constants
#define S_   2048
#define E_   1024
#define H_   16
#define DH_  64
#define KNB  64
#define E3_  (3*E_)
#define MASKV (-1e10f)

// Scratch (allocation-free rule: __device__ globals)
__device__ float g_qkv[(size_t)S_ * E3_];     // [S, 3E]  (q | k | v)
__device__ float g_attn[(size_t)S_ * E_];     // [S, E]   attention output (pre out-proj)

// ---------------------------------------------------------------------------
// SGEMM (NT): C[M,N] = A[M,K] @ B[N,K]^T + bias[N]
// BM=128 BN=128 BK=16, 256 threads, 8x8 per thread
// ---------------------------------------------------------------------------
#define BM 128
#define BN 128
#define BK 16
#define TM 8
#define TN 8

__global__ __launch_bounds__(256)
void sgemm_nt_bias(const float* __restrict__ A, const float* __restrict__ B,
                   const float* __restrict__ bias, float* __restrict__ C,
                   int M, int N, int K)
{
    __shared__ float As[BK][BM];
    __shared__ float Bs[BK][BN];

    const int tid = threadIdx.x;
    const int tx = tid & 15;   // 0..15  (N groups)
    const int ty = tid >> 4;   // 0..15  (M groups)
    const int m0 = blockIdx.y * BM;
    const int n0 = blockIdx.x * BN;

    float acc[TM][TN];
#pragma unroll
    for (int i = 0; i < TM; i++)
#pragma unroll
        for (int j = 0; j < TN; j++) acc[i][j] = 0.f;

    for (int k0 = 0; k0 < K; k0 += BK) {
        // load A tile (128x16) and B tile (128x16), transposed into smem
#pragma unroll
        for (int l = 0; l < 2; l++) {
            int idx = tid + l * 256;        // 0..511
            int row = idx >> 2;             // 0..127
            int c4  = idx & 3;              // 0..3
            float4 a = *(const float4*)(A + (size_t)(m0 + row) * K + k0 + c4 * 4);
            As[c4 * 4 + 0][row] = a.x;
            As[c4 * 4 + 1][row] = a.y;
            As[c4 * 4 + 2][row] = a.z;
            As[c4 * 4 + 3][row] = a.w;
            float4 b = *(const float4*)(B + (size_t)(n0 + row) * K + k0 + c4 * 4);
            Bs[c4 * 4 + 0][row] = b.x;
            Bs[c4 * 4 + 1][row] = b.y;
            Bs[c4 * 4 + 2][row] = b.z;
            Bs[c4 * 4 + 3][row] = b.w;
        }
        __syncthreads();

#pragma unroll
        for (int kk = 0; kk < BK; kk++) {
            float ra[TM], rb[TN];
            *(float4*)&ra[0] = *(const float4*)&As[kk][ty * TM];
            *(float4*)&ra[4] = *(const float4*)&As[kk][ty * TM + 4];
            *(float4*)&rb[0] = *(const float4*)&Bs[kk][tx * TN];
            *(float4*)&rb[4] = *(const float4*)&Bs[kk][tx * TN + 4];
#pragma unroll
            for (int i = 0; i < TM; i++)
#pragma unroll
                for (int j = 0; j < TN; j++)
                    acc[i][j] = fmaf(ra[i], rb[j], acc[i][j]);
        }
        __syncthreads();
    }

    // epilogue: + bias, vectorized stores
#pragma unroll
    for (int i = 0; i < TM; i++) {
        int m = m0 + ty * TM + i;
#pragma unroll
        for (int j = 0; j < TN; j += 4) {
            int n = n0 + tx * TN + j;
            float4 o;
            o.x = acc[i][j + 0] + bias[n + 0];
            o.y = acc[i][j + 1] + bias[n + 1];
            o.z = acc[i][j + 2] + bias[n + 2];
            o.w = acc[i][j + 3] + bias[n + 3];
            *(float4*)(C + (size_t)m * N + n) = o;
        }
    }
}

// ---------------------------------------------------------------------------
// Banded scores + softmax + attn@V
// One block handles (head h, 8 consecutive query rows).
// Band union for 8 rows: up to 144 key rows -> smem, reused 8x.
// Writes: full masked scores row (2048 floats each) + attn output tile.
// ---------------------------------------------------------------------------
#define TI   8
#define NUMAX 144   // TI + 2*KNB + ... (8 + 128 = 136, pad to 144 for stride)
#define NT   256

__global__ __launch_bounds__(NT)
void scores_attn_kernel(const float* __restrict__ qkv,
                        float* __restrict__ scores_out,
                        float* __restrict__ attn_out)
{
    __shared__ float KVs[NUMAX * 65];       // K rows, later reused for V rows
    __shared__ float Qs[TI * 65];
    __shared__ float Sc[TI * NUMAX];        // raw scores, then probabilities

    const int h  = blockIdx.y;
    const int i0 = blockIdx.x * TI;
    const int t  = threadIdx.x;

    const int j0 = max(0, i0 - KNB);
    const int j1 = min(S_ - 1, i0 + TI - 1 + KNB);
    const int NU = j1 - j0 + 1;             // <= 136

    const int hoff = h * DH_;

    // load Q tile [TI x 64]
    for (int idx = t; idx < TI * DH_; idx += NT) {
        int r = idx >> 6, d = idx & 63;
        Qs[r * 65 + d] = qkv[(size_t)(i0 + r) * E3_ + hoff + d];
    }
    // load K band [NU x 64]
    for (int idx = t; idx < NU * DH_; idx += NT) {
        int u = idx >> 6, d = idx & 63;
        KVs[u * 65 + d] = qkv[(size_t)(j0 + u) * E3_ + E_ + hoff + d];
    }
    __syncthreads();

    // scores: thread t owns key column u=t (if t < NU), computes all TI rows
    if (t < NU) {
        const int j = j0 + t;
#pragma unroll
        for (int r = 0; r < TI; r++) {
            const int i = i0 + r;
            float val;
            if (abs(i - j) <= KNB) {
                float s = 0.f;
#pragma unroll
                for (int d = 0; d < DH_; d++)
                    s = fmaf(Qs[r * 65 + d], KVs[t * 65 + d], s);
                val = s * 0.125f;           // DH^-0.5
            } else {
                val = -INFINITY;            // sentinel; replaced by MASKV on store
            }
            Sc[r * NUMAX + t] = val;
        }
    }
    __syncthreads();

    // write full masked scores rows to gmem (coalesced)
#pragma unroll
    for (int r = 0; r < TI; r++) {
        const int i = i0 + r;
        const size_t base = ((size_t)h * S_ + i) * S_;
        for (int j = t; j < S_; j += NT) {
            float v = MASKV;
            if (j >= i - KNB && j <= i + KNB)
                v = Sc[r * NUMAX + (j - j0)];
            scores_out[base + j] = v;
        }
    }

    // softmax per row: one warp per row (8 warps)
    const int w = t >> 5, lane = t & 31;
    if (w < TI) {
        float m = -INFINITY;
        for (int u = lane; u < NU; u += 32)
            m = fmaxf(m, Sc[w * NUMAX + u]);
#pragma unroll
        for (int o = 16; o; o >>= 1)
            m = fmaxf(m, __shfl_xor_sync(0xFFFFFFFFu, m, o));
        float ssum = 0.f;
        for (int u = lane; u < NU; u += 32) {
            float e = expf(Sc[w * NUMAX + u] - m);   // -inf -> 0, matches ref
            Sc[w * NUMAX + u] = e;
            ssum += e;
        }
#pragma unroll
        for (int o = 16; o; o >>= 1)
            ssum += __shfl_xor_sync(0xFFFFFFFFu, ssum, o);
        float inv = 1.f / ssum;
        for (int u = lane; u < NU; u += 32)
            Sc[w * NUMAX + u] *= inv;
    }
    __syncthreads();

    // load V band into same smem buffer
    for (int idx = t; idx < NU * DH_; idx += NT) {
        int u = idx >> 6, d = idx & 63;
        KVs[u * 65 + d] = qkv[(size_t)(j0 + u) * E3_ + 2 * E_ + hoff + d];
    }
    __syncthreads();

    // attn @ V : 8x64 outputs, 256 threads -> 2 outputs each
    {
        const int d  = t & 63;
        const int rr = t >> 6;              // 0..3
#pragma unroll
        for (int s = 0; s < 2; s++) {
            const int r = rr + s * 4;
            float acc = 0.f;
            for (int u = 0; u < NU; u++)
                acc = fmaf(Sc[r * NUMAX + u], KVs[u * 65 + d], acc);
            attn_out[(size_t)(i0 + r) * E_ + hoff + d] = acc;
        }
    }
}

// ---------------------------------------------------------------------------
// launch
// ---------------------------------------------------------------------------
extern "C" void kernel_launch(void* const* d_in, const int* in_sizes, int n_in,
                              void* d_out, int out_size)
{
    const float* x     = (const float*)d_in[0];   // [S, E]
    const float* W_qkv = (const float*)d_in[1];   // [3E, E]
    const float* b_qkv = (const float*)d_in[2];   // [3E]
    const float* W_out = (const float*)d_in[3];   // [E, E]
    const float* b_out = (const float*)d_in[4];   // [E]

    float* out_ptr    = (float*)d_out;                        // [S, E]
    float* scores_ptr = out_ptr + (size_t)S_ * E_;            // [H, S, S]

    float* qkv_ptr;
    float* attn_ptr;
    cudaGetSymbolAddress((void**)&qkv_ptr,  g_qkv);
    cudaGetSymbolAddress((void**)&attn_ptr, g_attn);

    // 1) QKV projection: [2048,1024] @ [3072,1024]^T + b
    {
        dim3 grid(E3_ / BN, S_ / BM);
        sgemm_nt_bias<<<grid, 256>>>(x, W_qkv, b_qkv, qkv_ptr, S_, E3_, E_);
    }

    // 2) banded scores + softmax + attn@V
    {
        dim3 grid(S_ / TI, H_);
        scores_attn_kernel<<<grid, NT>>>(qkv_ptr, scores_ptr, attn_ptr);
    }

    // 3) output projection: [2048,1024] @ [1024,1024]^T + b
    {
        dim3 grid(E_ / BN, S_ / BM);
        sgemm_nt_bias<<<grid, 256>>>(attn_ptr, W_out, b_out, out_ptr, S_, E_, E_);
    }
}

// round 2
// speedup vs baseline: 1.2187x; 1.2187x over previous
#include <cuda_runtime.h>
#include <cstdint>
#include <math.h>

// Problem constants
#define S_   2048
#define E_   1024
#define H_   16
#define DH_  64
#define KNB  64
#define E3_  (3*E_)
#define MASKV (-1e10f)

// Scratch (allocation-free rule: __device__ globals)
__device__ float g_qkv[(size_t)S_ * E3_];     // [S, 3E]  (q | k | v)
__device__ float g_attn[(size_t)S_ * E_];     // [S, E]   attention output (pre out-proj)

// ---------------------------------------------------------------------------
// SGEMM (NT): C[M,N] = A[M,K] @ B[N,K]^T + bias[N]
// BM=128 BN=128 BK=16, 256 threads, 8x8 per thread.
// Double-buffered smem + packed fma.rn.f32x2 (sm_103a).
// ---------------------------------------------------------------------------
#define BM 128
#define BN 128
#define BK 16
#define TM 8
#define TN 8

__device__ __forceinline__ unsigned long long pack2(float lo, float hi) {
    unsigned long long r;
    asm("mov.b64 %0, {%1, %2};" : "=l"(r) : "f"(lo), "f"(hi));
    return r;
}
__device__ __forceinline__ void unpack2(unsigned long long v, float& lo, float& hi) {
    asm("mov.b64 {%0, %1}, %2;" : "=f"(lo), "=f"(hi) : "l"(v));
}
__device__ __forceinline__ void ffma2(unsigned long long& d,
                                      unsigned long long a,
                                      unsigned long long b) {
    asm("fma.rn.f32x2 %0, %1, %2, %0;" : "+l"(d) : "l"(a), "l"(b));
}

__global__ __launch_bounds__(256, 2)
void sgemm_nt_bias(const float* __restrict__ A, const float* __restrict__ B,
                   const float* __restrict__ bias, float* __restrict__ C,
                   int M, int N, int K)
{
    __shared__ float As[2][BK][BM];
    __shared__ float Bs[2][BK][BN];

    const int tid = threadIdx.x;
    const int tx = tid & 15;   // 0..15  (N groups)
    const int ty = tid >> 4;   // 0..15  (M groups)
    const int m0 = blockIdx.y * BM;
    const int n0 = blockIdx.x * BN;

    // per-thread global-load coords (2 chunks of 256 threads cover 128x16 tile)
    const int row0 = tid >> 2;            // 0..63   (l=0)
    const int row1 = row0 + 64;           // 64..127 (l=1)
    const int c4   = (tid & 3) * 4;       // 0,4,8,12

    unsigned long long accp[TM][TN / 2];
#pragma unroll
    for (int i = 0; i < TM; i++)
#pragma unroll
        for (int j = 0; j < TN / 2; j++) accp[i][j] = 0ULL;

    float4 pa0, pa1, pb0, pb1;

    // prefetch k0=0 into stage 0
    pa0 = *(const float4*)(A + (size_t)(m0 + row0) * K + c4);
    pa1 = *(const float4*)(A + (size_t)(m0 + row1) * K + c4);
    pb0 = *(const float4*)(B + (size_t)(n0 + row0) * K + c4);
    pb1 = *(const float4*)(B + (size_t)(n0 + row1) * K + c4);
    {
        As[0][c4 + 0][row0] = pa0.x; As[0][c4 + 1][row0] = pa0.y;
        As[0][c4 + 2][row0] = pa0.z; As[0][c4 + 3][row0] = pa0.w;
        As[0][c4 + 0][row1] = pa1.x; As[0][c4 + 1][row1] = pa1.y;
        As[0][c4 + 2][row1] = pa1.z; As[0][c4 + 3][row1] = pa1.w;
        Bs[0][c4 + 0][row0] = pb0.x; Bs[0][c4 + 1][row0] = pb0.y;
        Bs[0][c4 + 2][row0] = pb0.z; Bs[0][c4 + 3][row0] = pb0.w;
        Bs[0][c4 + 0][row1] = pb1.x; Bs[0][c4 + 1][row1] = pb1.y;
        Bs[0][c4 + 2][row1] = pb1.z; Bs[0][c4 + 3][row1] = pb1.w;
    }
    __syncthreads();

    for (int k0 = 0; k0 < K; k0 += BK) {
        const int s  = (k0 / BK) & 1;
        const int kn = k0 + BK;
        const bool more = (kn < K);

        if (more) {
            pa0 = *(const float4*)(A + (size_t)(m0 + row0) * K + kn + c4);
            pa1 = *(const float4*)(A + (size_t)(m0 + row1) * K + kn + c4);
            pb0 = *(const float4*)(B + (size_t)(n0 + row0) * K + kn + c4);
            pb1 = *(const float4*)(B + (size_t)(n0 + row1) * K + kn + c4);
        }

#pragma unroll
        for (int kk = 0; kk < BK; kk++) {
            float ra[TM];
            *(float4*)&ra[0] = *(const float4*)&As[s][kk][ty * TM];
            *(float4*)&ra[4] = *(const float4*)&As[s][kk][ty * TM + 4];
            float4 b0 = *(const float4*)&Bs[s][kk][tx * TN];
            float4 b1 = *(const float4*)&Bs[s][kk][tx * TN + 4];
            unsigned long long rbp[4];
            rbp[0] = pack2(b0.x, b0.y);
            rbp[1] = pack2(b0.z, b0.w);
            rbp[2] = pack2(b1.x, b1.y);
            rbp[3] = pack2(b1.z, b1.w);
#pragma unroll
            for (int i = 0; i < TM; i++) {
                unsigned long long rap = pack2(ra[i], ra[i]);
#pragma unroll
                for (int j = 0; j < TN / 2; j++)
                    ffma2(accp[i][j], rap, rbp[j]);
            }
        }

        if (more) {
            const int sn = s ^ 1;
            As[sn][c4 + 0][row0] = pa0.x; As[sn][c4 + 1][row0] = pa0.y;
            As[sn][c4 + 2][row0] = pa0.z; As[sn][c4 + 3][row0] = pa0.w;
            As[sn][c4 + 0][row1] = pa1.x; As[sn][c4 + 1][row1] = pa1.y;
            As[sn][c4 + 2][row1] = pa1.z; As[sn][c4 + 3][row1] = pa1.w;
            Bs[sn][c4 + 0][row0] = pb0.x; Bs[sn][c4 + 1][row0] = pb0.y;
            Bs[sn][c4 + 2][row0] = pb0.z; Bs[sn][c4 + 3][row0] = pb0.w;
            Bs[sn][c4 + 0][row1] = pb1.x; Bs[sn][c4 + 1][row1] = pb1.y;
            Bs[sn][c4 + 2][row1] = pb1.z; Bs[sn][c4 + 3][row1] = pb1.w;
        }
        __syncthreads();
    }

    // epilogue: + bias, vectorized stores
#pragma unroll
    for (int i = 0; i < TM; i++) {
        int m = m0 + ty * TM + i;
#pragma unroll
        for (int j = 0; j < TN; j += 4) {
            int n = n0 + tx * TN + j;
            float a0, a1, a2, a3;
            unpack2(accp[i][j / 2],     a0, a1);
            unpack2(accp[i][j / 2 + 1], a2, a3);
            float4 o;
            o.x = a0 + bias[n + 0];
            o.y = a1 + bias[n + 1];
            o.z = a2 + bias[n + 2];
            o.w = a3 + bias[n + 3];
            *(float4*)(C + (size_t)m * N + n) = o;
        }
    }
}

// ---------------------------------------------------------------------------
// Banded scores + softmax + attn@V
// One block handles (head h, 8 consecutive query rows).
// ---------------------------------------------------------------------------
#define TI   8
#define NUMAX 144
#define NT   256

__global__ __launch_bounds__(NT)
void scores_attn_kernel(const float* __restrict__ qkv,
                        float* __restrict__ scores_out,
                        float* __restrict__ attn_out)
{
    __shared__ float KVs[NUMAX * 65];       // K rows, later reused for V rows
    __shared__ float Qs[TI * 65];
    __shared__ float Sc[TI * NUMAX];        // raw scores, then probabilities

    const int h  = blockIdx.y;
    const int i0 = blockIdx.x * TI;
    const int t  = threadIdx.x;

    const int j0 = max(0, i0 - KNB);
    const int j1 = min(S_ - 1, i0 + TI - 1 + KNB);
    const int NU = j1 - j0 + 1;             // <= 136

    const int hoff = h * DH_;

    // load Q tile [TI x 64]
    for (int idx = t; idx < TI * DH_; idx += NT) {
        int r = idx >> 6, d = idx & 63;
        Qs[r * 65 + d] = qkv[(size_t)(i0 + r) * E3_ + hoff + d];
    }
    // load K band [NU x 64]
    for (int idx = t; idx < NU * DH_; idx += NT) {
        int u = idx >> 6, d = idx & 63;
        KVs[u * 65 + d] = qkv[(size_t)(j0 + u) * E3_ + E_ + hoff + d];
    }
    __syncthreads();

    // scores: thread t owns key column u=t (if t < NU), computes all TI rows
    if (t < NU) {
        const int j = j0 + t;
#pragma unroll
        for (int r = 0; r < TI; r++) {
            const int i = i0 + r;
            float val;
            if (abs(i - j) <= KNB) {
                float s = 0.f;
#pragma unroll
                for (int d = 0; d < DH_; d++)
                    s = fmaf(Qs[r * 65 + d], KVs[t * 65 + d], s);
                val = s * 0.125f;           // DH^-0.5
            } else {
                val = -INFINITY;            // sentinel; replaced by MASKV on store
            }
            Sc[r * NUMAX + t] = val;
        }
    }
    __syncthreads();

    // write full masked scores rows to gmem — float4 coalesced stores
#pragma unroll
    for (int r = 0; r < TI; r++) {
        const int i = i0 + r;
        const int lo = i - KNB, hi = i + KNB;
        float* rowp = scores_out + ((size_t)h * S_ + i) * S_;
#pragma unroll
        for (int it = 0; it < S_ / (NT * 4); it++) {
            const int j = (it * NT + t) * 4;
            float4 v;
            v.x = (j + 0 >= lo && j + 0 <= hi) ? Sc[r * NUMAX + (j + 0 - j0)] : MASKV;
            v.y = (j + 1 >= lo && j + 1 <= hi) ? Sc[r * NUMAX + (j + 1 - j0)] : MASKV;
            v.z = (j + 2 >= lo && j + 2 <= hi) ? Sc[r * NUMAX + (j + 2 - j0)] : MASKV;
            v.w = (j + 3 >= lo && j + 3 <= hi) ? Sc[r * NUMAX + (j + 3 - j0)] : MASKV;
            *(float4*)(rowp + j) = v;
        }
    }

    // softmax per row: one warp per row (8 warps)
    const int w = t >> 5, lane = t & 31;
    if (w < TI) {
        float m = -INFINITY;
        for (int u = lane; u < NU; u += 32)
            m = fmaxf(m, Sc[w * NUMAX + u]);
#pragma unroll
        for (int o = 16; o; o >>= 1)
            m = fmaxf(m, __shfl_xor_sync(0xFFFFFFFFu, m, o));
        float ssum = 0.f;
        for (int u = lane; u < NU; u += 32) {
            float e = expf(Sc[w * NUMAX + u] - m);   // -inf -> 0, matches ref
            Sc[w * NUMAX + u] = e;
            ssum += e;
        }
#pragma unroll
        for (int o = 16; o; o >>= 1)
            ssum += __shfl_xor_sync(0xFFFFFFFFu, ssum, o);
        float inv = 1.f / ssum;
        for (int u = lane; u < NU; u += 32)
            Sc[w * NUMAX + u] *= inv;
    }
    __syncthreads();

    // load V band into same smem buffer
    for (int idx = t; idx < NU * DH_; idx += NT) {
        int u = idx >> 6, d = idx & 63;
        KVs[u * 65 + d] = qkv[(size_t)(j0 + u) * E3_ + 2 * E_ + hoff + d];
    }
    __syncthreads();

    // attn @ V : 8x64 outputs, 256 threads -> 2 outputs each
    {
        const int d  = t & 63;
        const int rr = t >> 6;              // 0..3
#pragma unroll
        for (int s = 0; s < 2; s++) {
            const int r = rr + s * 4;
            float acc = 0.f;
            for (int u = 0; u < NU; u++)
                acc = fmaf(Sc[r * NUMAX + u], KVs[u * 65 + d], acc);
            attn_out[(size_t)(i0 + r) * E_ + hoff + d] = acc;
        }
    }
}

// ---------------------------------------------------------------------------
// launch
// ---------------------------------------------------------------------------
extern "C" void kernel_launch(void* const* d_in, const int* in_sizes, int n_in,
                              void* d_out, int out_size)
{
    const float* x     = (const float*)d_in[0];   // [S, E]
    const float* W_qkv = (const float*)d_in[1];   // [3E, E]
    const float* b_qkv = (const float*)d_in[2];   // [3E]
    const float* W_out = (const float*)d_in[3];   // [E, E]
    const float* b_out = (const float*)d_in[4];   // [E]

    float* out_ptr    = (float*)d_out;                        // [S, E]
    float* scores_ptr = out_ptr + (size_t)S_ * E_;            // [H, S, S]

    float* qkv_ptr;
    float* attn_ptr;
    cudaGetSymbolAddress((void**)&qkv_ptr,  g_qkv);
    cudaGetSymbolAddress((void**)&attn_ptr, g_attn);

    // 1) QKV projection: [2048,1024] @ [3072,1024]^T + b
    {
        dim3 grid(E3_ / BN, S_ / BM);
        sgemm_nt_bias<<<grid, 256>>>(x, W_qkv, b_qkv, qkv_ptr, S_, E3_, E_);
    }

    // 2) banded scores + softmax + attn@V
    {
        dim3 grid(S_ / TI, H_);
        scores_attn_kernel<<<grid, NT>>>(qkv_ptr, scores_ptr, attn_ptr);
    }

    // 3) output projection: [2048,1024] @ [1024,1024]^T + b
    {
        dim3 grid(E_ / BN, S_ / BM);
        sgemm_nt_bias<<<grid, 256>>>(attn_ptr, W_out, b_out, out_ptr, S_, E_, E_);
    }
}

// round 4
// speedup vs baseline: 1.9863x; 1.6299x over previous
#include <cuda_runtime.h>
#include <cuda_bf16.h>
#include <cstdint>
#include <math.h>

// Problem constants
#define S_   2048
#define E_   1024
#define H_   16
#define DH_  64
#define KNB  64
#define E3_  (3*E_)
#define MASKV (-1e10f)

// Scratch (__device__ globals; allocation-free rule)
__device__ float g_qkv[(size_t)S_ * E3_];     // [S, 3E]  (q | k | v)
__device__ float g_attn[(size_t)S_ * E_];     // [S, E]

// ---------------------------------------------------------------------------
// bf16-split tensor-core GEMM (NT): C[M,N] = A[M,K] @ B[N,K]^T + bias[N]
// fp32 accuracy via 2-term bf16 split (AhBh + AhBl + AlBh).
// Tile 128x128x32, 8 warps (64x32 warp tiles), double-buffered smem.
// mma.sync.m16n8k16 bf16 + ldmatrix (baseline PTX, compiles for sm_103).
// ---------------------------------------------------------------------------
#define ROWB   80                    // bytes per 32-bf16 row (pad 32->40 bf16)
#define TILEB  (128 * ROWB)          // 10240 B per bf16 tile
#define STAGEB (4 * TILEB)           // Ah, Al, Bh, Bl
#define GSMEM  (2 * STAGEB)          // 81920 B

__device__ __forceinline__ uint32_t smem_u32(const void* p) {
    uint32_t a;
    asm("{ .reg .u64 t; cvta.to.shared.u64 t, %1; cvt.u32.u64 %0, t; }" : "=r"(a) : "l"(p));
    return a;
}

#define LDSM4(r, a) \
    asm volatile("ldmatrix.sync.aligned.m8n8.x4.shared.b16 {%0,%1,%2,%3}, [%4];" \
        : "=r"((r)[0]), "=r"((r)[1]), "=r"((r)[2]), "=r"((r)[3]) : "r"(a))

__device__ __forceinline__ void mma16816(float* d, const uint32_t* a, const uint32_t* b) {
    asm volatile("mma.sync.aligned.m16n8k16.row.col.f32.bf16.bf16.f32 "
        "{%0,%1,%2,%3}, {%4,%5,%6,%7}, {%8,%9}, {%0,%1,%2,%3};"
        : "+f"(d[0]), "+f"(d[1]), "+f"(d[2]), "+f"(d[3])
        : "r"(a[0]), "r"(a[1]), "r"(a[2]), "r"(a[3]), "r"(b[0]), "r"(b[1]));
}

// split float4 -> 4x bf16 hi + 4x bf16 lo
__device__ __forceinline__ void split4(float4 v, uint2& h, uint2& l) {
    __nv_bfloat162 h0 = __float22bfloat162_rn(make_float2(v.x, v.y));
    __nv_bfloat162 h1 = __float22bfloat162_rn(make_float2(v.z, v.w));
    float2 f0 = __bfloat1622float2(h0);
    float2 f1 = __bfloat1622float2(h1);
    __nv_bfloat162 l0 = __float22bfloat162_rn(make_float2(v.x - f0.x, v.y - f0.y));
    __nv_bfloat162 l1 = __float22bfloat162_rn(make_float2(v.z - f1.x, v.w - f1.y));
    h.x = *(uint32_t*)&h0; h.y = *(uint32_t*)&h1;
    l.x = *(uint32_t*)&l0; l.y = *(uint32_t*)&l1;
}

__global__ __launch_bounds__(256)
void bf16_gemm_nt_bias(const float* __restrict__ A, const float* __restrict__ B,
                       const float* __restrict__ bias, float* __restrict__ C,
                       int M, int N, int K)
{
    extern __shared__ char sm[];
    const uint32_t sbase = smem_u32(sm);

    const int tid  = threadIdx.x;
    const int lane = tid & 31;
    const int wid  = tid >> 5;
    const int wm   = (wid >> 2) * 64;   // warp m offset within 128
    const int wn   = (wid & 3) * 32;    // warp n offset within 128
    const int m0   = blockIdx.y * 128;
    const int n0   = blockIdx.x * 128;

    float d[4][4][4];
#pragma unroll
    for (int i = 0; i < 4; i++)
#pragma unroll
        for (int j = 0; j < 4; j++)
#pragma unroll
            for (int q = 0; q < 4; q++) d[i][j][q] = 0.f;

    // per-thread staging coords: 1024 float4 per tile-pair -> 4 each
    const int srow = tid >> 3;          // 0..31 (+32*i)
    const int sq   = tid & 7;           // 16B chunk

    float4 ra[4], rb[4];

    auto gload = [&](int k0) {
#pragma unroll
        for (int i = 0; i < 4; i++) {
            int row = srow + i * 32;
            ra[i] = *(const float4*)(A + (size_t)(m0 + row) * K + k0 + sq * 4);
            rb[i] = *(const float4*)(B + (size_t)(n0 + row) * K + k0 + sq * 4);
        }
    };
    auto sstore = [&](int s) {
        char* base = sm + s * STAGEB;
#pragma unroll
        for (int i = 0; i < 4; i++) {
            int row = srow + i * 32;
            uint32_t off = row * ROWB + sq * 8;
            uint2 h, l;
            split4(ra[i], h, l);
            *(uint2*)(base + off)          = h;
            *(uint2*)(base + TILEB + off)  = l;
            split4(rb[i], h, l);
            *(uint2*)(base + 2 * TILEB + off) = h;
            *(uint2*)(base + 3 * TILEB + off) = l;
        }
    };

    auto compute = [&](int s) {
        const uint32_t sb = sbase + s * STAGEB;
#pragma unroll
        for (int ks = 0; ks < 2; ks++) {
            const uint32_t colb = (ks * 16 + ((lane >> 4) << 3)) * 2;

            // B fragments (hi & lo): 2 ldmatrix.x4 groups cover n 0..31
            uint32_t bh[4][2], bl[4][2];
#pragma unroll
            for (int ng = 0; ng < 2; ng++) {
                uint32_t addr = sb + 2 * TILEB
                              + (wn + ng * 16 + (lane & 15)) * ROWB + colb;
                uint32_t r[4];
                LDSM4(r, addr);
                bh[ng * 2 + 0][0] = r[0]; bh[ng * 2 + 0][1] = r[2];
                bh[ng * 2 + 1][0] = r[1]; bh[ng * 2 + 1][1] = r[3];
                LDSM4(r, addr + TILEB);
                bl[ng * 2 + 0][0] = r[0]; bl[ng * 2 + 0][1] = r[2];
                bl[ng * 2 + 1][0] = r[1]; bl[ng * 2 + 1][1] = r[3];
            }

#pragma unroll
            for (int mt = 0; mt < 4; mt++) {
                uint32_t addr = sb + (wm + mt * 16 + (lane & 15)) * ROWB + colb;
                uint32_t ah[4], al[4];
                LDSM4(ah, addr);
                LDSM4(al, addr + TILEB);
#pragma unroll
                for (int nt = 0; nt < 4; nt++) {
                    mma16816(d[mt][nt], ah, bh[nt]);
                    mma16816(d[mt][nt], ah, bl[nt]);
                    mma16816(d[mt][nt], al, bh[nt]);
                }
            }
        }
    };

    // prologue
    gload(0);
    sstore(0);
    __syncthreads();

    const int NC = K / 32;
    for (int c = 0; c < NC; c++) {
        const int s = c & 1;
        if (c + 1 < NC) gload((c + 1) * 32);
        compute(s);
        if (c + 1 < NC) sstore(s ^ 1);
        __syncthreads();
    }

    // epilogue
#pragma unroll
    for (int mt = 0; mt < 4; mt++) {
        const int r0 = m0 + wm + mt * 16 + (lane >> 2);
#pragma unroll
        for (int nt = 0; nt < 4; nt++) {
            const int c0 = n0 + wn + nt * 8 + (lane & 3) * 2;
            const float b0 = bias[c0], b1 = bias[c0 + 1];
            float2 o;
            o.x = d[mt][nt][0] + b0;
            o.y = d[mt][nt][1] + b1;
            *(float2*)(C + (size_t)r0 * N + c0) = o;
            o.x = d[mt][nt][2] + b0;
            o.y = d[mt][nt][3] + b1;
            *(float2*)(C + (size_t)(r0 + 8) * N + c0) = o;
        }
    }
}

// ---------------------------------------------------------------------------
// Banded scores + softmax + attn@V  (unchanged from R2)
// ---------------------------------------------------------------------------
#define TI   8
#define NUMAX 144
#define NT   256

__global__ __launch_bounds__(NT)
void scores_attn_kernel(const float* __restrict__ qkv,
                        float* __restrict__ scores_out,
                        float* __restrict__ attn_out)
{
    __shared__ float KVs[NUMAX * 65];
    __shared__ float Qs[TI * 65];
    __shared__ float Sc[TI * NUMAX];

    const int h  = blockIdx.y;
    const int i0 = blockIdx.x * TI;
    const int t  = threadIdx.x;

    const int j0 = max(0, i0 - KNB);
    const int j1 = min(S_ - 1, i0 + TI - 1 + KNB);
    const int NU = j1 - j0 + 1;

    const int hoff = h * DH_;

    for (int idx = t; idx < TI * DH_; idx += NT) {
        int r = idx >> 6, dd = idx & 63;
        Qs[r * 65 + dd] = qkv[(size_t)(i0 + r) * E3_ + hoff + dd];
    }
    for (int idx = t; idx < NU * DH_; idx += NT) {
        int u = idx >> 6, dd = idx & 63;
        KVs[u * 65 + dd] = qkv[(size_t)(j0 + u) * E3_ + E_ + hoff + dd];
    }
    __syncthreads();

    if (t < NU) {
        const int j = j0 + t;
#pragma unroll
        for (int r = 0; r < TI; r++) {
            const int i = i0 + r;
            float val;
            if (abs(i - j) <= KNB) {
                float s = 0.f;
#pragma unroll
                for (int dd = 0; dd < DH_; dd++)
                    s = fmaf(Qs[r * 65 + dd], KVs[t * 65 + dd], s);
                val = s * 0.125f;
            } else {
                val = -INFINITY;
            }
            Sc[r * NUMAX + t] = val;
        }
    }
    __syncthreads();

#pragma unroll
    for (int r = 0; r < TI; r++) {
        const int i = i0 + r;
        const int lo = i - KNB, hi = i + KNB;
        float* rowp = scores_out + ((size_t)h * S_ + i) * S_;
#pragma unroll
        for (int it = 0; it < S_ / (NT * 4); it++) {
            const int j = (it * NT + t) * 4;
            float4 v;
            v.x = (j + 0 >= lo && j + 0 <= hi) ? Sc[r * NUMAX + (j + 0 - j0)] : MASKV;
            v.y = (j + 1 >= lo && j + 1 <= hi) ? Sc[r * NUMAX + (j + 1 - j0)] : MASKV;
            v.z = (j + 2 >= lo && j + 2 <= hi) ? Sc[r * NUMAX + (j + 2 - j0)] : MASKV;
            v.w = (j + 3 >= lo && j + 3 <= hi) ? Sc[r * NUMAX + (j + 3 - j0)] : MASKV;
            *(float4*)(rowp + j) = v;
        }
    }

    const int w = t >> 5, lane = t & 31;
    if (w < TI) {
        float m = -INFINITY;
        for (int u = lane; u < NU; u += 32)
            m = fmaxf(m, Sc[w * NUMAX + u]);
#pragma unroll
        for (int o = 16; o; o >>= 1)
            m = fmaxf(m, __shfl_xor_sync(0xFFFFFFFFu, m, o));
        float ssum = 0.f;
        for (int u = lane; u < NU; u += 32) {
            float e = expf(Sc[w * NUMAX + u] - m);
            Sc[w * NUMAX + u] = e;
            ssum += e;
        }
#pragma unroll
        for (int o = 16; o; o >>= 1)
            ssum += __shfl_xor_sync(0xFFFFFFFFu, ssum, o);
        float inv = 1.f / ssum;
        for (int u = lane; u < NU; u += 32)
            Sc[w * NUMAX + u] *= inv;
    }
    __syncthreads();

    for (int idx = t; idx < NU * DH_; idx += NT) {
        int u = idx >> 6, dd = idx & 63;
        KVs[u * 65 + dd] = qkv[(size_t)(j0 + u) * E3_ + 2 * E_ + hoff + dd];
    }
    __syncthreads();

    {
        const int dd = t & 63;
        const int rr = t >> 6;
#pragma unroll
        for (int s = 0; s < 2; s++) {
            const int r = rr + s * 4;
            float acc = 0.f;
            for (int u = 0; u < NU; u++)
                acc = fmaf(Sc[r * NUMAX + u], KVs[u * 65 + dd], acc);
            attn_out[(size_t)(i0 + r) * E_ + hoff + dd] = acc;
        }
    }
}

// ---------------------------------------------------------------------------
// launch
// ---------------------------------------------------------------------------
extern "C" void kernel_launch(void* const* d_in, const int* in_sizes, int n_in,
                              void* d_out, int out_size)
{
    const float* x     = (const float*)d_in[0];   // [S, E]
    const float* W_qkv = (const float*)d_in[1];   // [3E, E]
    const float* b_qkv = (const float*)d_in[2];   // [3E]
    const float* W_out = (const float*)d_in[3];   // [E, E]
    const float* b_out = (const float*)d_in[4];   // [E]

    float* out_ptr    = (float*)d_out;                 // [S, E]
    float* scores_ptr = out_ptr + (size_t)S_ * E_;     // [H, S, S]

    float *qkv_p, *attn_p;
    cudaGetSymbolAddress((void**)&qkv_p,  g_qkv);
    cudaGetSymbolAddress((void**)&attn_p, g_attn);

    static bool attr_set = false;
    cudaFuncSetAttribute(bf16_gemm_nt_bias,
                         cudaFuncAttributeMaxDynamicSharedMemorySize, GSMEM);
    (void)attr_set;

    // 1) QKV projection: [2048,3072] = x @ Wqkv^T + b
    {
        dim3 grid(E3_ / 128, S_ / 128);
        bf16_gemm_nt_bias<<<grid, 256, GSMEM>>>(x, W_qkv, b_qkv, qkv_p,
                                                S_, E3_, E_);
    }

    // 2) banded scores + softmax + attn@V
    {
        dim3 grid(S_ / TI, H_);
        scores_attn_kernel<<<grid, NT>>>(qkv_p, scores_ptr, attn_p);
    }

    // 3) output projection: [2048,1024] = attn @ Wout^T + b
    {
        dim3 grid(E_ / 128, S_ / 128);
        bf16_gemm_nt_bias<<<grid, 256, GSMEM>>>(attn_p, W_out, b_out, out_ptr,
                                                S_, E_, E_);
    }
}